// round 4
// baseline (speedup 1.0000x reference)
#include <cuda_runtime.h>
#include <math.h>

// Problem constants
#define B_  32
#define A_  3
#define S_  80
#define NC_ 80
#define CH_ 85
#define NCELLS (B_*A_*S_*S_)   // 614400
#define EPS_ 1e-7f
#define LS_  0.1f
#define INV_PI2_4 0.40528473456935109f   // 4/pi^2
#define FULLM 0xffffffffu

#define TPB 256
#define CPW 64                           // cells per warp (2 chunks of 32)
#define CPB (TPB / 32 * CPW)             // 512
#define NBLK (NCELLS / CPB)              // 1200 -> 8 CTA/SM, 1 full wave

// Global accumulators: {noobj_loss, noobj_cnt, box_loss, obj_loss, cls_loss, obj_cnt}
// Statically zero-initialized; the finalizing block resets them so every graph
// replay starts from identical state.
__device__ float        g_acc[6];
__device__ unsigned int g_ticket;

__device__ __forceinline__ float softplus_f(float z) {
    // max(z,0) + log(1+exp(-|z|))  (fast intrinsics; tol is 1e-3, err ~1e-7)
    return fmaxf(z, 0.0f) + __logf(1.0f + __expf(-fabsf(z)));
}

__device__ __forceinline__ float wredsum(float v) {
#pragma unroll
    for (int o = 16; o; o >>= 1) v += __shfl_xor_sync(FULLM, v, o);
    return v;
}

// Warp-collective heavy path for one obj cell c (p0 passed via register shfl).
__device__ __forceinline__ void heavy_cell(
    int c, float p0, int lane,
    const float* __restrict__ pred, const float* __restrict__ target,
    const float* __restrict__ anchors,
    float& boxS, float& objS, float& clsS)
{
    const float* p = pred + (size_t)c * CH_;
    const float* t = target + (size_t)c * 6;

    // 80 class logits: lanes cover 32 + 32 + 16 (coalesced)
    float c0 = __ldg(&p[5 + lane]);
    float c1 = __ldg(&p[37 + lane]);
    float c2 = (lane < 16) ? __ldg(&p[69 + lane]) : 0.0f;

    // logits ~ N(0,1): direct sum-exp safe (no max shift)
    float se = __expf(c0) + __expf(c1) + ((lane < 16) ? __expf(c2) : 0.0f);
    float sl = c0 + c1 + ((lane < 16) ? c2 : 0.0f);
    se = wredsum(se);
    sl = wredsum(sl);
    float lse = __logf(se);

    int kcls = (int)__ldg(&t[5]);                 // warp-uniform
    float vsel = (kcls < 32) ? c0 : ((kcls < 64) ? c1 : c2);
    float py = __shfl_sync(FULLM, vsel, kcls & 31);

    clsS += lse - (1.0f - LS_) * py - (LS_ / (float)NC_) * sl;

    // Objectness quirk: BCE-with-logits fed sigmoid(p0), t0==1:
    // bce(s,1) = log(1+exp(-s)),  s = sigmoid(p0)
    float sg = 1.0f / (1.0f + __expf(-p0));
    objS += __logf(1.0f + __expf(-sg));

    // Box decode + CIoU (warp-uniform broadcast loads, redundant per-lane flops)
    float cx1 = 1.0f / (1.0f + __expf(-__ldg(&p[1])));
    float cy1 = 1.0f / (1.0f + __expf(-__ldg(&p[2])));
    int a = (c / (S_ * S_)) % A_;
    float w1 = __expf(__ldg(&p[3])) * __ldg(&anchors[2 * a]);
    float h1 = __expf(__ldg(&p[4])) * __ldg(&anchors[2 * a + 1]);
    float cx2 = __ldg(&t[1]), cy2 = __ldg(&t[2]);
    float w2  = __ldg(&t[3]), h2  = __ldg(&t[4]);

    float x1a = cx1 - 0.5f * w1, x1b = cx1 + 0.5f * w1;
    float y1a = cy1 - 0.5f * h1, y1b = cy1 + 0.5f * h1;
    float x2a = cx2 - 0.5f * w2, x2b = cx2 + 0.5f * w2;
    float y2a = cy2 - 0.5f * h2, y2b = cy2 + 0.5f * h2;

    float iw = fmaxf(fminf(x1b, x2b) - fmaxf(x1a, x2a), 0.0f);
    float ih = fmaxf(fminf(y1b, y2b) - fmaxf(y1a, y2a), 0.0f);
    float inter = iw * ih;
    float uni   = w1 * h1 + w2 * h2 - inter + EPS_;
    float iou   = __fdividef(inter, uni);

    float cw  = fmaxf(x1b, x2b) - fminf(x1a, x2a);
    float chh = fmaxf(y1b, y2b) - fminf(y1a, y2a);
    float c2d = cw * cw + chh * chh + EPS_;
    float dx = cx2 - cx1, dy = cy2 - cy1;
    float rho2 = dx * dx + dy * dy;

    float dat = atanf(__fdividef(w2, h2 + EPS_)) - atanf(__fdividef(w1, h1 + EPS_));
    float vv = INV_PI2_4 * dat * dat;
    float alpha = __fdividef(vv, 1.0f - iou + vv + EPS_);
    float ciou = iou - __fdividef(rho2, c2d) - alpha * vv;

    boxS += 1.0f - ciou;
}

__global__ __launch_bounds__(TPB)
void yolo_fused_kernel(const float* __restrict__ pred,
                       const float* __restrict__ target,
                       const float* __restrict__ anchors,
                       float* __restrict__ out) {
    __shared__ float s_acc[6];   // {noobjL, noobjN, boxL, objL, clsL, objN}
    __shared__ int   s_last;

    const int tid  = threadIdx.x;
    const int wid  = tid >> 5;
    const int lane = tid & 31;
    if (tid < 6) s_acc[tid] = 0.0f;
    if (tid == 0) s_last = 0;
    __syncthreads();

    // Each warp autonomously owns 64 contiguous cells (2 chunks of 32).
    // No block-level sync until the final reduction: warps slide freely so
    // one warp's phase-2 latency chain overlaps another's load burst.
    const int wbase = blockIdx.x * CPB + wid * CPW;

    // Front-batched loads for both chunks (4 independent LDGs -> MLP).
    float t0a = __ldg(&target[(size_t)(wbase + lane) * 6]);
    float t0b = __ldg(&target[(size_t)(wbase + 32 + lane) * 6]);
    float p0a = __ldg(&pred[(size_t)(wbase + lane) * CH_]);
    float p0b = __ldg(&pred[(size_t)(wbase + 32 + lane) * CH_]);

    float noobjL = 0.0f, boxS = 0.0f, objS = 0.0f, clsS = 0.0f;
    int   objN = 0;

    // ---- chunk A ----
    if (t0a == 0.0f) noobjL += softplus_f(p0a);
    unsigned mA = __ballot_sync(FULLM, t0a == 1.0f);
    objN += __popc(mA);
    while (mA) {
        int b = __ffs(mA) - 1; mA &= mA - 1;
        float p0c = __shfl_sync(FULLM, p0a, b);
        heavy_cell(wbase + b, p0c, lane, pred, target, anchors, boxS, objS, clsS);
    }
    // ---- chunk B ----
    if (t0b == 0.0f) noobjL += softplus_f(p0b);
    unsigned mB = __ballot_sync(FULLM, t0b == 1.0f);
    objN += __popc(mB);
    while (mB) {
        int b = __ffs(mB) - 1; mB &= mB - 1;
        float p0c = __shfl_sync(FULLM, p0b, b);
        heavy_cell(wbase + 32 + b, p0c, lane, pred, target, anchors, boxS, objS, clsS);
    }

    // noobjL is per-lane; everything else is already warp-uniform.
    noobjL = wredsum(noobjL);
    if (lane == 0) {
        atomicAdd(&s_acc[0], noobjL);
        atomicAdd(&s_acc[1], (float)(CPW - objN));  // targets are exactly 0 or 1
        atomicAdd(&s_acc[2], boxS);
        atomicAdd(&s_acc[3], objS);
        atomicAdd(&s_acc[4], clsS);
        atomicAdd(&s_acc[5], (float)objN);
    }
    __syncthreads();

    // ---------- Block partial -> global, ticket-based finalize -----------------
    if (tid < 6) atomicAdd(&g_acc[tid], s_acc[tid]);
    __threadfence();
    __syncthreads();
    if (tid == 0) {
        unsigned int tk = atomicAdd(&g_ticket, 1u);
        if (tk == NBLK - 1) s_last = 1;
    }
    __syncthreads();

    if (s_last && tid == 0) {
        float acc[6];
#pragma unroll
        for (int i = 0; i < 6; i++) acc[i] = atomicAdd(&g_acc[i], 0.0f);
        float objNt   = fmaxf(acc[5], 1.0f);
        float noobjNt = fmaxf(acc[1], 1.0f);
        out[0] = 2.0f * acc[2] / objNt     // box
               + acc[3] / objNt            // object
               + acc[0] / noobjNt          // no-object
               + acc[4] / objNt;           // class
        // Reset for next graph replay.
#pragma unroll
        for (int i = 0; i < 6; i++) g_acc[i] = 0.0f;
        __threadfence();
        g_ticket = 0u;
    }
}

extern "C" void kernel_launch(void* const* d_in, const int* in_sizes, int n_in,
                              void* d_out, int out_size) {
    const float* pred    = (const float*)d_in[0];
    const float* target  = (const float*)d_in[1];
    const float* anchors = (const float*)d_in[2];
    float* out = (float*)d_out;
    (void)in_sizes; (void)n_in; (void)out_size;

    yolo_fused_kernel<<<NBLK, TPB>>>(pred, target, anchors, out);
}

// round 5
// speedup vs baseline: 1.3125x; 1.3125x over previous
#include <cuda_runtime.h>
#include <math.h>

// Problem constants
#define B_  32
#define A_  3
#define S_  80
#define NC_ 80
#define CH_ 85
#define NCELLS (B_*A_*S_*S_)   // 614400
#define EPS_ 1e-7f
#define LS_  0.1f
#define INV_PI2_4 0.40528473456935109f   // 4/pi^2
#define FULLM 0xffffffffu

#define TPB 256
#define CPB 512                          // cells per block
#define NBLK (NCELLS / CPB)              // 1200 -> ~8 CTA/SM, 1 full wave

// Global accumulators: {noobj_loss, noobj_cnt, box_loss, obj_loss, cls_loss, obj_cnt}
__device__ float        g_acc[6];
__device__ unsigned int g_ticket;

__device__ __forceinline__ float softplus_f(float z) {
    return fmaxf(z, 0.0f) + __logf(1.0f + __expf(-fabsf(z)));
}

__device__ __forceinline__ float wredsum(float v) {
#pragma unroll
    for (int o = 16; o; o >>= 1) v += __shfl_xor_sync(FULLM, v, o);
    return v;
}

// atan for x > 0, ~1e-5 abs error (minimax poly on [0,1] + reflection)
__device__ __forceinline__ float fast_atan_pos(float x) {
    float t = (x > 1.0f) ? __fdividef(1.0f, x) : x;
    float s = t * t;
    float p = -0.0117212f;
    p = p * s + 0.0526533f;
    p = p * s - 0.1164329f;
    p = p * s + 0.1935435f;
    p = p * s - 0.3326235f;
    p = p * s + 0.9999773f;
    float r = t * p;
    return (x > 1.0f) ? (1.57079633f - r) : r;
}

__global__ __launch_bounds__(TPB)
void yolo_fused_kernel(const float* __restrict__ pred,
                       const float* __restrict__ target,
                       const float* __restrict__ anchors,
                       float* __restrict__ out) {
    __shared__ int   s_list[CPB];
    __shared__ int   s_cnt;
    __shared__ float s_acc[6];   // {noobjL, noobjN, boxL, objL, clsL, objN}
    __shared__ int   s_last;

    const int tid  = threadIdx.x;
    const int wid  = tid >> 5;
    const int lane = tid & 31;
    if (tid == 0) { s_cnt = 0; s_last = 0; }
    if (tid < 6) s_acc[tid] = 0.0f;
    __syncthreads();

    const int base = blockIdx.x * CPB;

    // ---------- Phase 1: thread-per-cell light pass + obj compaction ----------
    float t0v[CPB / TPB];
    float p0v[CPB / TPB];
#pragma unroll
    for (int k = 0; k < CPB / TPB; k++) {
        int c = base + k * TPB + tid;
        t0v[k] = __ldg(&target[(size_t)c * 6]);
        p0v[k] = __ldg(&pred[(size_t)c * CH_]);
    }
    float noobjL = 0.0f;
    int   noobjN = 0;
#pragma unroll
    for (int k = 0; k < CPB / TPB; k++) {
        int c = base + k * TPB + tid;
        if (t0v[k] == 0.0f) {
            noobjL += softplus_f(p0v[k]);
            noobjN++;
        } else if (t0v[k] == 1.0f) {
            int pos = atomicAdd(&s_cnt, 1);
            s_list[pos] = c;
        }
    }
    noobjL = wredsum(noobjL);
    float noobjNf = wredsum((float)noobjN);
    if (lane == 0) {
        atomicAdd(&s_acc[0], noobjL);
        atomicAdd(&s_acc[1], noobjNf);
    }
    __syncthreads();

    // ---------- Phase 2: HALF-WARP per obj cell (2 cells per warp iter) -------
    const int nObj = s_cnt;
    const int half = lane >> 4;      // 0 or 1
    const int hl   = lane & 15;      // lane within half

    float boxS = 0.0f, objS = 0.0f, clsS = 0.0f;

    const int nPair = (nObj + 1) >> 1;
    for (int i = wid; i < nPair; i += TPB / 32) {
        const int  ci    = 2 * i + half;
        const bool valid = (ci < nObj);
        const int  c     = s_list[valid ? ci : 0];   // safe: loop implies nObj>0
        const float* p = pred + (size_t)c * CH_;
        const float* t = target + (size_t)c * 6;

        // 80 class logits: 16 lanes x 5 loads (coalesced >=64B within half)
        float c0 = __ldg(&p[5 + hl]);
        float c1 = __ldg(&p[21 + hl]);
        float c2 = __ldg(&p[37 + hl]);
        float c3 = __ldg(&p[53 + hl]);
        float c4 = __ldg(&p[69 + hl]);

        // logits ~ N(0,1): direct sum-exp safe
        float se = __expf(c0) + __expf(c1) + __expf(c2) + __expf(c3) + __expf(c4);
        float sl = c0 + c1 + c2 + c3 + c4;
        // 4-step butterfly stays within each 16-lane half
#pragma unroll
        for (int o = 8; o; o >>= 1) {
            se += __shfl_xor_sync(FULLM, se, o);
            sl += __shfl_xor_sync(FULLM, sl, o);
        }
        float lse = __logf(se);

        int kcls = (int)__ldg(&t[5]);                // half-uniform
        int grp  = kcls >> 4;                        // 0..4
        float vsel = (grp == 0) ? c0 : (grp == 1) ? c1 : (grp == 2) ? c2
                   : (grp == 3) ? c3 : c4;
        float py = __shfl_sync(FULLM, vsel, (half << 4) | (kcls & 15));

        // Objectness quirk: bce(sigmoid(p0), 1) = log(1+exp(-sigmoid(p0)))
        float p0 = __ldg(&p[0]);
        float sg = 1.0f / (1.0f + __expf(-p0));

        // Box decode + CIoU (half-uniform broadcast loads)
        float cx1 = 1.0f / (1.0f + __expf(-__ldg(&p[1])));
        float cy1 = 1.0f / (1.0f + __expf(-__ldg(&p[2])));
        int a = (c / (S_ * S_)) % A_;
        float w1 = __expf(__ldg(&p[3])) * __ldg(&anchors[2 * a]);
        float h1 = __expf(__ldg(&p[4])) * __ldg(&anchors[2 * a + 1]);
        float cx2 = __ldg(&t[1]), cy2 = __ldg(&t[2]);
        float w2  = __ldg(&t[3]), h2  = __ldg(&t[4]);

        float x1a = cx1 - 0.5f * w1, x1b = cx1 + 0.5f * w1;
        float y1a = cy1 - 0.5f * h1, y1b = cy1 + 0.5f * h1;
        float x2a = cx2 - 0.5f * w2, x2b = cx2 + 0.5f * w2;
        float y2a = cy2 - 0.5f * h2, y2b = cy2 + 0.5f * h2;

        float iw = fmaxf(fminf(x1b, x2b) - fmaxf(x1a, x2a), 0.0f);
        float ih = fmaxf(fminf(y1b, y2b) - fmaxf(y1a, y2a), 0.0f);
        float inter = iw * ih;
        float uni   = w1 * h1 + w2 * h2 - inter + EPS_;
        float iou   = __fdividef(inter, uni);

        float cw  = fmaxf(x1b, x2b) - fminf(x1a, x2a);
        float chh = fmaxf(y1b, y2b) - fminf(y1a, y2a);
        float c2d = cw * cw + chh * chh + EPS_;
        float dx = cx2 - cx1, dy = cy2 - cy1;
        float rho2 = dx * dx + dy * dy;

        float dat = fast_atan_pos(__fdividef(w2, h2 + EPS_))
                  - fast_atan_pos(__fdividef(w1, h1 + EPS_));
        float vv = INV_PI2_4 * dat * dat;
        float alpha = __fdividef(vv, 1.0f - iou + vv + EPS_);
        float ciou = iou - __fdividef(rho2, c2d) - alpha * vv;

        if (valid) {
            clsS += lse - (1.0f - LS_) * py - (LS_ / (float)NC_) * sl;
            objS += __logf(1.0f + __expf(-sg));
            boxS += 1.0f - ciou;
        }
    }

    // Values are identical within each half; combine halves, then lane 0 commits.
    boxS += __shfl_xor_sync(FULLM, boxS, 16);
    objS += __shfl_xor_sync(FULLM, objS, 16);
    clsS += __shfl_xor_sync(FULLM, clsS, 16);
    if (lane == 0) {
        atomicAdd(&s_acc[2], boxS);
        atomicAdd(&s_acc[3], objS);
        atomicAdd(&s_acc[4], clsS);
    }
    __syncthreads();

    // ---------- Block partial -> global, ticket-based finalize -----------------
    if (tid < 5) atomicAdd(&g_acc[tid], s_acc[tid]);
    if (tid == 5) atomicAdd(&g_acc[5], (float)nObj);
    __threadfence();
    __syncthreads();
    if (tid == 0) {
        unsigned int tk = atomicAdd(&g_ticket, 1u);
        if (tk == NBLK - 1) s_last = 1;
    }
    __syncthreads();

    if (s_last && tid == 0) {
        float acc[6];
#pragma unroll
        for (int i = 0; i < 6; i++) acc[i] = atomicAdd(&g_acc[i], 0.0f);
        float objNt   = fmaxf(acc[5], 1.0f);
        float noobjNt = fmaxf(acc[1], 1.0f);
        out[0] = 2.0f * acc[2] / objNt     // box
               + acc[3] / objNt            // object
               + acc[0] / noobjNt          // no-object
               + acc[4] / objNt;           // class
        // Reset for next graph replay.
#pragma unroll
        for (int i = 0; i < 6; i++) g_acc[i] = 0.0f;
        __threadfence();
        g_ticket = 0u;
    }
}

extern "C" void kernel_launch(void* const* d_in, const int* in_sizes, int n_in,
                              void* d_out, int out_size) {
    const float* pred    = (const float*)d_in[0];
    const float* target  = (const float*)d_in[1];
    const float* anchors = (const float*)d_in[2];
    float* out = (float*)d_out;
    (void)in_sizes; (void)n_in; (void)out_size;

    yolo_fused_kernel<<<NBLK, TPB>>>(pred, target, anchors, out);
}